// round 5
// baseline (speedup 1.0000x reference)
// mma.sync fp16 fused GEMM+epilogue, v2: 64x64 warp tiles, single-barrier mainloop,
// cp.async issued ahead of compute, double-buffered ldmatrix fragments.
//   out = relu(1 - beta + X@W^T); res = relu(1 - beta_res + x + out); leaky==id.
// B=N=K=4096 fp32; X,W pre-converted RN to fp16 (11-bit significand == tf32).

#include <cuda_runtime.h>
#include <cuda_fp16.h>
#include <cstdint>

#define DIM     4096
#define BM      128
#define BN      128
#define BK      64                     // halves per chunk = 128 bytes per row
#define STAGES  3
#define NT      128                    // 4 warps, each 64x64
#define NC      (DIM / BK)             // 64 k-chunks
#define AB_TILE (BM * BK * 2)          // 16384 bytes
#define STAGE_BYTES (2 * AB_TILE)      // 32768
#define SMEM_TOTAL  (STAGES * STAGE_BYTES)  // 98304 -> 2 CTAs/SM

// ------------------------------------------------------------------ scratch
__device__ __half g_Xh[(size_t)DIM * DIM];
__device__ __half g_Wh[(size_t)DIM * DIM];

// ------------------------------------------------------------------ helpers
__device__ __forceinline__ uint32_t smem_u32(const void* p) {
    uint32_t a;
    asm("{ .reg .u64 t; cvta.to.shared.u64 t, %1; cvt.u32.u64 %0, t; }" : "=r"(a) : "l"(p));
    return a;
}
__device__ __forceinline__ void cp16(uint32_t saddr, const void* gaddr) {
    asm volatile("cp.async.cg.shared.global [%0], [%1], 16;"
                 :: "r"(saddr), "l"(gaddr) : "memory");
}
__device__ __forceinline__ void cp_commit() {
    asm volatile("cp.async.commit_group;" ::: "memory");
}
template <int N>
__device__ __forceinline__ void cp_wait() {
    asm volatile("cp.async.wait_group %0;" :: "n"(N) : "memory");
}
__device__ __forceinline__ void ldsm4(uint32_t* r, uint32_t addr) {
    asm volatile("ldmatrix.sync.aligned.m8n8.x4.shared.b16 {%0,%1,%2,%3}, [%4];"
                 : "=r"(r[0]), "=r"(r[1]), "=r"(r[2]), "=r"(r[3]) : "r"(addr));
}
__device__ __forceinline__ void mma_f16(float* d, const uint32_t* a, const uint32_t* b) {
    asm volatile(
        "mma.sync.aligned.m16n8k16.row.col.f32.f16.f16.f32 "
        "{%0,%1,%2,%3}, {%4,%5,%6,%7}, {%8,%9}, {%0,%1,%2,%3};"
        : "+f"(d[0]), "+f"(d[1]), "+f"(d[2]), "+f"(d[3])
        : "r"(a[0]), "r"(a[1]), "r"(a[2]), "r"(a[3]), "r"(b[0]), "r"(b[1]));
}

// ------------------------------------------------------------------ prep kernel
// grid.y = 0 -> X, 1 -> W. 8 floats -> 8 halves per thread.
__global__ void __launch_bounds__(256) to_half2_kernel(const float* __restrict__ x,
                                                       const float* __restrict__ w,
                                                       __half* __restrict__ xh,
                                                       __half* __restrict__ wh) {
    const float* in  = blockIdx.y ? w : x;
    __half* outp     = blockIdx.y ? wh : xh;
    size_t i = ((size_t)blockIdx.x * blockDim.x + threadIdx.x) * 8;
    float4 v0 = *reinterpret_cast<const float4*>(in + i);
    float4 v1 = *reinterpret_cast<const float4*>(in + i + 4);
    __half2 h0 = __floats2half2_rn(v0.x, v0.y);
    __half2 h1 = __floats2half2_rn(v0.z, v0.w);
    __half2 h2 = __floats2half2_rn(v1.x, v1.y);
    __half2 h3 = __floats2half2_rn(v1.z, v1.w);
    uint4 o;
    o.x = *reinterpret_cast<uint32_t*>(&h0);
    o.y = *reinterpret_cast<uint32_t*>(&h1);
    o.z = *reinterpret_cast<uint32_t*>(&h2);
    o.w = *reinterpret_cast<uint32_t*>(&h3);
    *reinterpret_cast<uint4*>(outp + i) = o;
}

// ------------------------------------------------------------------ main kernel
__global__ void __launch_bounds__(NT, 2)
resfc_mma_f16_v2(const __half* __restrict__ Ah,
                 const __half* __restrict__ Bh,
                 const float* __restrict__ X,
                 const float* __restrict__ beta,
                 const float* __restrict__ beta_res,
                 float* __restrict__ out)
{
    extern __shared__ __align__(1024) char smem[];
    const uint32_t sbase = smem_u32(smem);
    const int tid = threadIdx.x;
    const int l   = tid & 31;
    const int wid = tid >> 5;             // 0..3
    const int warpM = (wid & 1) * 64;     // 2 warps in M
    const int warpN = (wid >> 1) * 64;    // 2 warps in N
    const int bm = blockIdx.y * BM;
    const int bn = blockIdx.x * BN;

    // ---- cp.async mapping: 128 threads x 8 passes x (A16B + B16B) per stage
    const int grow = tid >> 3;            // row 0..15 (+16 per pass)
    const int gcol = tid & 7;             // 16B granule within 128B row
    const __half* gA = Ah + (size_t)(bm + grow) * DIM + gcol * 8;
    const __half* gB = Bh + (size_t)(bn + grow) * DIM + gcol * 8;
    const uint32_t scol = (uint32_t)(gcol * 16);

    // ---- ldmatrix per-thread terms (SW128 swizzle within tile)
    const uint32_t xorv   = (uint32_t)(l & 7) << 4;
    const uint32_t aRow   = (uint32_t)(warpM + (l & 15));
    const uint32_t aByteH = (uint32_t)(l & 16);            // 0 or 16
    const uint32_t bRow   = (uint32_t)(warpN + (l & 7) + ((l >> 1) & 8));
    const uint32_t bByteH = (uint32_t)((l & 8) << 1);      // 0 or 16

    float acc[4][8][4];
    #pragma unroll
    for (int i = 0; i < 4; ++i)
        #pragma unroll
        for (int j = 0; j < 8; ++j)
            #pragma unroll
            for (int k = 0; k < 4; ++k)
                acc[i][j][k] = 0.0f;

    uint32_t aF[2][4][4];
    uint32_t bF[2][8][2];

    #define ISSUE(c, stage) do {                                              \
        const uint32_t sa_ = sbase + (uint32_t)(stage) * STAGE_BYTES;         \
        const __half* ga_ = gA + (size_t)(c) * BK;                            \
        const __half* gb_ = gB + (size_t)(c) * BK;                            \
        _Pragma("unroll")                                                     \
        for (int p_ = 0; p_ < 8; ++p_) {                                      \
            const uint32_t r_  = (uint32_t)(grow + p_ * 16);                  \
            const uint32_t so_ = r_ * 128 + (scol ^ ((r_ & 7) << 4));         \
            cp16(sa_ + so_,            ga_ + (size_t)p_ * 16 * DIM);          \
            cp16(sa_ + AB_TILE + so_,  gb_ + (size_t)p_ * 16 * DIM);          \
        }                                                                     \
    } while (0)

    #define LOAD_FRAGS(s, buf) do {                                           \
        const uint32_t aoff_ = ((uint32_t)((s) * 32) + aByteH) ^ xorv;        \
        const uint32_t boff_ = ((uint32_t)((s) * 32) + bByteH) ^ xorv;        \
        _Pragma("unroll")                                                     \
        for (int t_ = 0; t_ < 4; ++t_)                                        \
            ldsm4(aF[buf][t_], aBase + (uint32_t)t_ * 2048 + aoff_);          \
        _Pragma("unroll")                                                     \
        for (int u_ = 0; u_ < 4; ++u_) {                                      \
            uint32_t r_[4];                                                   \
            ldsm4(r_, bBase + (uint32_t)u_ * 2048 + boff_);                   \
            bF[buf][2 * u_][0]     = r_[0];  bF[buf][2 * u_][1]     = r_[1];  \
            bF[buf][2 * u_ + 1][0] = r_[2];  bF[buf][2 * u_ + 1][1] = r_[3];  \
        }                                                                     \
    } while (0)

    #define COMPUTE(buf) do {                                                 \
        _Pragma("unroll")                                                     \
        for (int mt_ = 0; mt_ < 4; ++mt_)                                     \
            _Pragma("unroll")                                                 \
            for (int nt_ = 0; nt_ < 8; ++nt_)                                 \
                mma_f16(acc[mt_][nt_], aF[buf][mt_], bF[buf][nt_]);           \
    } while (0)

    // -------- prologue: fill STAGES-1 stages --------
    ISSUE(0, 0); cp_commit();
    ISSUE(1, 1); cp_commit();

    int stage = 0;
    for (int c = 0; c < NC; ++c) {
        cp_wait<STAGES - 2>();
        __syncthreads();                  // single barrier per chunk

        // issue chunk c+2 BEFORE compute; its stage held chunk c-1, whose
        // compute finished before this barrier. Always commit one group.
        const int cn = c + STAGES - 1;
        if (cn < NC) {
            const int sn = (stage + STAGES - 1) % STAGES;
            ISSUE(cn, sn);
        }
        cp_commit();

        const uint32_t aBase = sbase + (uint32_t)stage * STAGE_BYTES + aRow * 128;
        const uint32_t bBase = sbase + (uint32_t)stage * STAGE_BYTES + AB_TILE + bRow * 128;

        LOAD_FRAGS(0, 0);
        #pragma unroll
        for (int s = 0; s < 4; ++s) {     // 4 x k16 per 64-half chunk
            if (s < 3) LOAD_FRAGS(s + 1, (s + 1) & 1);
            COMPUTE(s & 1);
        }

        if (++stage == STAGES) stage = 0;
    }
    #undef ISSUE
    #undef LOAD_FRAGS
    #undef COMPUTE

    // -------- fused epilogue --------
    const float one_mb = 1.0f - beta[0];
    const int colB = bn + warpN + 2 * (l & 3);

    float2 br2[8];
    #pragma unroll
    for (int nt = 0; nt < 8; ++nt)
        br2[nt] = *reinterpret_cast<const float2*>(beta_res + colB + nt * 8);

    #pragma unroll
    for (int mt = 0; mt < 4; ++mt) {
        #pragma unroll
        for (int h = 0; h < 2; ++h) {
            const int row = bm + warpM + mt * 16 + (l >> 2) + h * 8;
            const float* xr  = X   + (size_t)row * DIM + colB;
            float*       orw = out + (size_t)row * DIM + colB;
            #pragma unroll
            for (int nt = 0; nt < 8; ++nt) {
                float2 xv = *reinterpret_cast<const float2*>(xr + nt * 8);
                const float d0 = acc[mt][nt][h * 2 + 0];
                const float d1 = acc[mt][nt][h * 2 + 1];
                const float o0 = fmaxf(one_mb + d0, 0.0f);
                const float o1 = fmaxf(one_mb + d1, 0.0f);
                const float r0 = fmaxf(1.0f - (br2[nt].x - (xv.x + o0)), 0.0f);
                const float r1 = fmaxf(1.0f - (br2[nt].y - (xv.y + o1)), 0.0f);
                *reinterpret_cast<float2*>(orw + nt * 8) = make_float2(r0, r1);
            }
        }
    }
}

// ------------------------------------------------------------------ host side
extern "C" void kernel_launch(void* const* d_in, const int* in_sizes, int n_in,
                              void* d_out, int out_size)
{
    const float* X        = (const float*)d_in[0];
    const float* W        = (const float*)d_in[1];
    const float* beta     = (const float*)d_in[2];
    const float* beta_res = (const float*)d_in[3];
    float* out            = (float*)d_out;

    void *pXh = nullptr, *pWh = nullptr;
    cudaGetSymbolAddress(&pXh, g_Xh);
    cudaGetSymbolAddress(&pWh, g_Wh);

    dim3 pgrid(DIM * DIM / (256 * 8), 2);
    to_half2_kernel<<<pgrid, 256>>>(X, W, (__half*)pXh, (__half*)pWh);

    cudaFuncSetAttribute(resfc_mma_f16_v2,
                         cudaFuncAttributeMaxDynamicSharedMemorySize, SMEM_TOTAL);
    dim3 grid(DIM / BN, DIM / BM);   // 32 x 32
    resfc_mma_f16_v2<<<grid, NT, SMEM_TOTAL>>>((const __half*)pXh, (const __half*)pWh,
                                               X, beta, beta_res, out);
}

// round 6
// speedup vs baseline: 1.0872x; 1.0872x over previous
// mma.sync fp16 fused GEMM+epilogue, v3: R4's 8-warp 64x32 warp-tile shape
// (2 CTAs/SM, <=128 regs) + R5's single-barrier mainloop with early cp.async issue.
//   out = relu(1 - beta + X@W^T); res = relu(1 - beta_res + x + out); leaky==id.
// B=N=K=4096 fp32; X,W pre-converted RN to fp16 (11-bit significand == tf32).

#include <cuda_runtime.h>
#include <cuda_fp16.h>
#include <cstdint>

#define DIM     4096
#define BM      128
#define BN      128
#define BK      64                     // halves per chunk = 128 bytes per row
#define STAGES  3
#define NT      256                    // 8 warps, each 64x32
#define NC      (DIM / BK)             // 64 k-chunks
#define AB_TILE (BM * BK * 2)          // 16384 bytes
#define STAGE_BYTES (2 * AB_TILE)      // 32768
#define SMEM_TOTAL  (STAGES * STAGE_BYTES)  // 98304 -> 2 CTAs/SM

// ------------------------------------------------------------------ scratch
__device__ __half g_Xh[(size_t)DIM * DIM];
__device__ __half g_Wh[(size_t)DIM * DIM];

// ------------------------------------------------------------------ helpers
__device__ __forceinline__ uint32_t smem_u32(const void* p) {
    uint32_t a;
    asm("{ .reg .u64 t; cvta.to.shared.u64 t, %1; cvt.u32.u64 %0, t; }" : "=r"(a) : "l"(p));
    return a;
}
__device__ __forceinline__ void cp16(uint32_t saddr, const void* gaddr) {
    asm volatile("cp.async.cg.shared.global [%0], [%1], 16;"
                 :: "r"(saddr), "l"(gaddr) : "memory");
}
__device__ __forceinline__ void cp_commit() {
    asm volatile("cp.async.commit_group;" ::: "memory");
}
template <int N>
__device__ __forceinline__ void cp_wait() {
    asm volatile("cp.async.wait_group %0;" :: "n"(N) : "memory");
}
__device__ __forceinline__ void ldsm4(uint32_t* r, uint32_t addr) {
    asm volatile("ldmatrix.sync.aligned.m8n8.x4.shared.b16 {%0,%1,%2,%3}, [%4];"
                 : "=r"(r[0]), "=r"(r[1]), "=r"(r[2]), "=r"(r[3]) : "r"(addr));
}
__device__ __forceinline__ void mma_f16(float* d, const uint32_t* a, const uint32_t* b) {
    asm volatile(
        "mma.sync.aligned.m16n8k16.row.col.f32.f16.f16.f32 "
        "{%0,%1,%2,%3}, {%4,%5,%6,%7}, {%8,%9}, {%0,%1,%2,%3};"
        : "+f"(d[0]), "+f"(d[1]), "+f"(d[2]), "+f"(d[3])
        : "r"(a[0]), "r"(a[1]), "r"(a[2]), "r"(a[3]), "r"(b[0]), "r"(b[1]));
}

// ------------------------------------------------------------------ prep kernel
// grid.y = 0 -> X, 1 -> W. 8 floats -> 8 halves per thread.
__global__ void __launch_bounds__(256) to_half2_kernel(const float* __restrict__ x,
                                                       const float* __restrict__ w,
                                                       __half* __restrict__ xh,
                                                       __half* __restrict__ wh) {
    const float* in  = blockIdx.y ? w : x;
    __half* outp     = blockIdx.y ? wh : xh;
    size_t i = ((size_t)blockIdx.x * blockDim.x + threadIdx.x) * 8;
    float4 v0 = *reinterpret_cast<const float4*>(in + i);
    float4 v1 = *reinterpret_cast<const float4*>(in + i + 4);
    __half2 h0 = __floats2half2_rn(v0.x, v0.y);
    __half2 h1 = __floats2half2_rn(v0.z, v0.w);
    __half2 h2 = __floats2half2_rn(v1.x, v1.y);
    __half2 h3 = __floats2half2_rn(v1.z, v1.w);
    uint4 o;
    o.x = *reinterpret_cast<uint32_t*>(&h0);
    o.y = *reinterpret_cast<uint32_t*>(&h1);
    o.z = *reinterpret_cast<uint32_t*>(&h2);
    o.w = *reinterpret_cast<uint32_t*>(&h3);
    *reinterpret_cast<uint4*>(outp + i) = o;
}

// ------------------------------------------------------------------ main kernel
__global__ void __launch_bounds__(NT, 2)
resfc_mma_f16_v3(const __half* __restrict__ Ah,
                 const __half* __restrict__ Bh,
                 const float* __restrict__ X,
                 const float* __restrict__ beta,
                 const float* __restrict__ beta_res,
                 float* __restrict__ out)
{
    extern __shared__ __align__(1024) char smem[];
    const uint32_t sbase = smem_u32(smem);
    const int tid = threadIdx.x;
    const int l   = tid & 31;
    const int wid = tid >> 5;             // 0..7
    const int warpM = (wid & 1) * 64;     // 2 warps in M
    const int warpN = (wid >> 1) * 32;    // 4 warps in N
    const int bm = blockIdx.y * BM;
    const int bn = blockIdx.x * BN;

    // ---- cp.async mapping: 256 threads x 4 passes x (A16B + B16B) per stage
    const int grow = tid >> 3;            // row 0..31 (+32 per pass)
    const int gcol = tid & 7;             // 16B granule within 128B row
    const __half* gA = Ah + (size_t)(bm + grow) * DIM + gcol * 8;
    const __half* gB = Bh + (size_t)(bn + grow) * DIM + gcol * 8;
    const uint32_t scol = (uint32_t)(gcol * 16);

    // ---- ldmatrix per-thread terms (SW128 swizzle within tile)
    const uint32_t xorv   = (uint32_t)(l & 7) << 4;
    const uint32_t aRow   = (uint32_t)(warpM + (l & 15));
    const uint32_t aByteH = (uint32_t)(l & 16);            // 0 or 16
    const uint32_t bRow   = (uint32_t)(warpN + (l & 7) + ((l >> 1) & 8));
    const uint32_t bByteH = (uint32_t)((l & 8) << 1);      // 0 or 16

    float acc[4][4][4];
    #pragma unroll
    for (int i = 0; i < 4; ++i)
        #pragma unroll
        for (int j = 0; j < 4; ++j)
            #pragma unroll
            for (int k = 0; k < 4; ++k)
                acc[i][j][k] = 0.0f;

    #define ISSUE(c, stage) do {                                              \
        const uint32_t sa_ = sbase + (uint32_t)(stage) * STAGE_BYTES;         \
        const __half* ga_ = gA + (size_t)(c) * BK;                            \
        const __half* gb_ = gB + (size_t)(c) * BK;                            \
        _Pragma("unroll")                                                     \
        for (int p_ = 0; p_ < 4; ++p_) {                                      \
            const uint32_t r_  = (uint32_t)(grow + p_ * 32);                  \
            const uint32_t so_ = r_ * 128 + (scol ^ ((r_ & 7) << 4));         \
            cp16(sa_ + so_,            ga_ + (size_t)p_ * 32 * DIM);          \
            cp16(sa_ + AB_TILE + so_,  gb_ + (size_t)p_ * 32 * DIM);          \
        }                                                                     \
    } while (0)

    // -------- prologue: fill STAGES-1 stages --------
    ISSUE(0, 0); cp_commit();
    ISSUE(1, 1); cp_commit();

    int stage = 0;
    for (int c = 0; c < NC; ++c) {
        cp_wait<STAGES - 2>();
        __syncthreads();                  // single barrier per chunk

        // Issue chunk c+2 BEFORE compute. Its stage held chunk c-1, whose
        // compute finished (program order) before the barrier above.
        const int cn = c + STAGES - 1;
        if (cn < NC) {
            const int sn = (stage + STAGES - 1) % STAGES;
            ISSUE(cn, sn);
        }
        cp_commit();                      // exactly one group per iteration

        const uint32_t aBase = sbase + (uint32_t)stage * STAGE_BYTES + aRow * 128;
        const uint32_t bBase = sbase + (uint32_t)stage * STAGE_BYTES + AB_TILE + bRow * 128;

        #pragma unroll
        for (int s = 0; s < 4; ++s) {     // 4 x k16 per 64-half chunk
            uint32_t aF[4][4];
            uint32_t bF[4][2];
            const uint32_t aoff = ((uint32_t)(s * 32) + aByteH) ^ xorv;
            const uint32_t boff = ((uint32_t)(s * 32) + bByteH) ^ xorv;
            #pragma unroll
            for (int t = 0; t < 4; ++t)
                ldsm4(aF[t], aBase + (uint32_t)t * 2048 + aoff);
            #pragma unroll
            for (int u = 0; u < 2; ++u) {
                uint32_t r[4];
                ldsm4(r, bBase + (uint32_t)u * 2048 + boff);
                bF[2 * u][0]     = r[0];  bF[2 * u][1]     = r[1];
                bF[2 * u + 1][0] = r[2];  bF[2 * u + 1][1] = r[3];
            }
            #pragma unroll
            for (int mt = 0; mt < 4; ++mt)
                #pragma unroll
                for (int nt = 0; nt < 4; ++nt)
                    mma_f16(acc[mt][nt], aF[mt], bF[nt]);
        }

        if (++stage == STAGES) stage = 0;
    }
    #undef ISSUE

    // -------- fused epilogue --------
    const float one_mb = 1.0f - beta[0];
    const int colB = bn + warpN + 2 * (l & 3);

    float2 br2[4];
    #pragma unroll
    for (int nt = 0; nt < 4; ++nt)
        br2[nt] = *reinterpret_cast<const float2*>(beta_res + colB + nt * 8);

    #pragma unroll
    for (int mt = 0; mt < 4; ++mt) {
        #pragma unroll
        for (int h = 0; h < 2; ++h) {
            const int row = bm + warpM + mt * 16 + (l >> 2) + h * 8;
            const float* xr  = X   + (size_t)row * DIM + colB;
            float*       orw = out + (size_t)row * DIM + colB;
            #pragma unroll
            for (int nt = 0; nt < 4; ++nt) {
                float2 xv = *reinterpret_cast<const float2*>(xr + nt * 8);
                const float d0 = acc[mt][nt][h * 2 + 0];
                const float d1 = acc[mt][nt][h * 2 + 1];
                const float o0 = fmaxf(one_mb + d0, 0.0f);
                const float o1 = fmaxf(one_mb + d1, 0.0f);
                const float r0 = fmaxf(1.0f - (br2[nt].x - (xv.x + o0)), 0.0f);
                const float r1 = fmaxf(1.0f - (br2[nt].y - (xv.y + o1)), 0.0f);
                *reinterpret_cast<float2*>(orw + nt * 8) = make_float2(r0, r1);
            }
        }
    }
}

// ------------------------------------------------------------------ host side
extern "C" void kernel_launch(void* const* d_in, const int* in_sizes, int n_in,
                              void* d_out, int out_size)
{
    const float* X        = (const float*)d_in[0];
    const float* W        = (const float*)d_in[1];
    const float* beta     = (const float*)d_in[2];
    const float* beta_res = (const float*)d_in[3];
    float* out            = (float*)d_out;

    void *pXh = nullptr, *pWh = nullptr;
    cudaGetSymbolAddress(&pXh, g_Xh);
    cudaGetSymbolAddress(&pWh, g_Wh);

    dim3 pgrid(DIM * DIM / (256 * 8), 2);
    to_half2_kernel<<<pgrid, 256>>>(X, W, (__half*)pXh, (__half*)pWh);

    cudaFuncSetAttribute(resfc_mma_f16_v3,
                         cudaFuncAttributeMaxDynamicSharedMemorySize, SMEM_TOTAL);
    dim3 grid(DIM / BN, DIM / BM);   // 32 x 32
    resfc_mma_f16_v3<<<grid, NT, SMEM_TOTAL>>>((const __half*)pXh, (const __half*)pWh,
                                               X, beta, beta_res, out);
}